// round 7
// baseline (speedup 1.0000x reference)
#include <cuda_runtime.h>
#include <cuda_bf16.h>

#define BATCH   2048
#define NTOK    49
#define CH      512
#define NHEADS  4
#define KDIM    32
#define DV      128
#define QO      192
#define EPS     1e-5f
#define FST     136      // feat / v row stride (bf16)
#define KQS     40       // k / q row stride (bf16)
#define ATS     72       // attn-prob row stride (bf16)
#define ASF     52       // attn fp32 score row stride
#define YQS     36       // conv-input fp32 stride
#define NROWS   ((size_t)BATCH * NTOK)   // 100352

// -------- global scratch --------
// h in proj-A-fragment tiled layout: [m16tile(6272)][kstep(32)][r16(16)][quad(4)] uint4
__device__ __align__(16) uint4 g_hA[NROWS * 128];
// proj weights, B-fragment permuted: [n8(64)][k16(32)][lane(32)] uint4 {bh.x,bh.y,bl.x,bl.y}
__device__ __align__(16) uint4 g_wB[64 * 32 * 32];
// qkv weights, B-fragment permuted: [head][j(24)][kstep(8)][lane(32)] uint2
__device__ __align__(16) uint2 g_qwB_hi[NHEADS * 24 * 8 * 32];
__device__ __align__(16) uint2 g_qwB_lo[NHEADS * 24 * 8 * 32];

// ==================== helpers ====================
__device__ __forceinline__ unsigned s2u(const void* p) {
    return (unsigned)__cvta_generic_to_shared(p);
}
__device__ __forceinline__ void ldsm_x4(unsigned* r, unsigned addr) {
    asm volatile("ldmatrix.sync.aligned.m8n8.x4.shared.b16 {%0,%1,%2,%3}, [%4];"
        : "=r"(r[0]), "=r"(r[1]), "=r"(r[2]), "=r"(r[3]) : "r"(addr));
}
__device__ __forceinline__ void ldsm_x4_t(unsigned* r, unsigned addr) {
    asm volatile("ldmatrix.sync.aligned.m8n8.x4.trans.shared.b16 {%0,%1,%2,%3}, [%4];"
        : "=r"(r[0]), "=r"(r[1]), "=r"(r[2]), "=r"(r[3]) : "r"(addr));
}
__device__ __forceinline__ void mma16816(float* c, const unsigned* a, const unsigned* b) {
    asm volatile("mma.sync.aligned.m16n8k16.row.col.f32.bf16.bf16.f32 "
        "{%0,%1,%2,%3}, {%4,%5,%6,%7}, {%8,%9}, {%0,%1,%2,%3};"
        : "+f"(c[0]), "+f"(c[1]), "+f"(c[2]), "+f"(c[3])
        : "r"(a[0]), "r"(a[1]), "r"(a[2]), "r"(a[3]), "r"(b[0]), "r"(b[1]));
}
__device__ __forceinline__ unsigned packbf2(float a, float b) {
    __nv_bfloat162 p = __halves2bfloat162(__float2bfloat16(a), __float2bfloat16(b));
    return *reinterpret_cast<unsigned*>(&p);
}
__device__ __forceinline__ void split2(float v0, float v1, unsigned& hp, unsigned& lp) {
    __nv_bfloat16 h0 = __float2bfloat16(v0), h1 = __float2bfloat16(v1);
    hp = (unsigned)__bfloat16_as_ushort(h0) | ((unsigned)__bfloat16_as_ushort(h1) << 16);
    lp = packbf2(v0 - __bfloat162float(h0), v1 - __bfloat162float(h1));
}
__device__ __forceinline__ void pref_l1(const void* p) {
    asm volatile("prefetch.global.L1 [%0];" :: "l"(p));
}

// ==================== prep kernels ====================
__global__ void wsplit_kernel(const float* __restrict__ w) {
    int i = blockIdx.x * 256 + threadIdx.x;       // 65536
    int j0 = i >> 10;
    int s_ = (i >> 5) & 31;
    int l  = i & 31;
    int n  = j0 * 8 + (l >> 2);
    int k0 = s_ * 16 + (l & 3) * 2;
    float a0 = w[n * 512 + k0],     a1 = w[n * 512 + k0 + 1];
    float a2 = w[n * 512 + k0 + 8], a3 = w[n * 512 + k0 + 9];
    uint4 p;
    split2(a0, a1, p.x, p.z);
    split2(a2, a3, p.y, p.w);
    g_wB[i] = p;
}

__global__ void qkvsplit_kernel(const float* __restrict__ w) {
    int i = blockIdx.x * 256 + threadIdx.x;       // 49152
    int h = i / (192 * 64);
    int rem = i % (192 * 64);
    int n = rem / 64;
    int p = rem % 64;
    float v0 = w[((size_t)h * 192 + n) * 128 + p * 2];
    float v1 = w[((size_t)h * 192 + n) * 128 + p * 2 + 1];
    unsigned hi, lo;
    split2(v0, v1, hi, lo);
    int j = n >> 3, kstep = p >> 3, q = p & 7;
    int r = q >> 2, lm4 = q & 3;
    int lane = (n & 7) * 4 + lm4;
    int base = ((h * 24 + j) * 8 + kstep) * 32 + lane;
    reinterpret_cast<unsigned*>(g_qwB_hi)[base * 2 + r] = hi;
    reinterpret_cast<unsigned*>(g_qwB_lo)[base * 2 + r] = lo;
}

// ==================== Phase A: cascaded heads (all-mma) ====================

struct __align__(16) SmemA {
    __nv_bfloat16 ah[64 * FST], al[64 * FST];
    __nv_bfloat16 vh[64 * FST], vl[64 * FST];
    union U1 {
        struct { __nv_bfloat16 kh[64 * KQS], kl[64 * KQS],
                               qh[64 * KQS], ql[64 * KQS]; } s1;
        struct { __nv_bfloat16 ath[64 * ATS], atl[64 * ATS]; } s2;
    } u1;
    union U2 { float attn[49 * ASF]; float yq[49 * YQS]; } u2;
    float dww[25 * 32];
    float qscale[QO], qbias[QO];
    float dws[KDIM], dwb[KDIM];
    float ab[NHEADS * NTOK];
};

__global__ void __launch_bounds__(256, 2) cascade_kernel(
    const float* __restrict__ x,
    const float* __restrict__ qkv_g,  const float* __restrict__ qkv_b,
    const float* __restrict__ qkv_m,  const float* __restrict__ qkv_v,
    const float* __restrict__ dw_w,   const float* __restrict__ dw_g,
    const float* __restrict__ dw_b,   const float* __restrict__ dw_m,
    const float* __restrict__ dw_v,   const float* __restrict__ attn_bias)
{
    extern __shared__ unsigned char smem_raw[];
    SmemA& s = *reinterpret_cast<SmemA*>(smem_raw);
    const int t    = threadIdx.x;
    const int b    = blockIdx.x;
    const int lane = t & 31;
    const int warp = t >> 5;
    const float scale = rsqrtf((float)KDIM);
    const size_t xoff = (size_t)b * NTOK * CH;

    for (int j = t; j < NHEADS * NTOK; j += 256) s.ab[j] = attn_bias[j];
    for (int j = t; j < 15 * FST; j += 256) {
        __nv_bfloat16 z = __float2bfloat16(0.f);
        s.ah[49 * FST + j] = z; s.al[49 * FST + j] = z;
        s.vh[49 * FST + j] = z; s.vl[49 * FST + j] = z;
    }
    if (t < 196) pref_l1(&x[xoff + (t >> 2) * CH + (t & 3) * 32]);

    const int a_r = lane & 15, a_c = (lane >> 4) * 8;
    const int b_r = (lane & 7) + ((lane & 16) ? 8 : 0);
    const int b_c = (lane & 8) ? 8 : 0;

    for (int head = 0; head < NHEADS; ++head) {
        // ---- feat update + hi/lo split ----
        for (int jdx = t; jdx < NTOK * 128; jdx += 256) {
            int n = jdx >> 7, d = jdx & 127;
            float v;
            if (head == 0) {
                v = x[xoff + n * CH + d];
            } else {
                v = __bfloat162float(s.ah[n * FST + d]) +
                    __bfloat162float(s.al[n * FST + d]) +
                    x[xoff + n * CH + head * 128 + d];
            }
            __nv_bfloat16 hv = __float2bfloat16(v);
            s.ah[n * FST + d] = hv;
            s.al[n * FST + d] = __float2bfloat16(v - __bfloat162float(hv));
        }
        // ---- BN folds ----
        if (t < QO) {
            float sc = qkv_g[head * QO + t] * rsqrtf(qkv_v[head * QO + t] + EPS);
            s.qscale[t] = sc;
            s.qbias[t]  = qkv_b[head * QO + t] - qkv_m[head * QO + t] * sc;
        } else if (t < QO + KDIM) {
            int c = t - QO;
            float sc = dw_g[head * KDIM + c] * rsqrtf(dw_v[head * KDIM + c] + EPS);
            s.dws[c] = sc;
            s.dwb[c] = dw_b[head * KDIM + c] - dw_m[head * KDIM + c] * sc;
        }
        for (int j = t; j < KDIM * 25; j += 256) {
            int c = j / 25, tap = j % 25;
            s.dww[tap * 32 + c] = dw_w[(head * KDIM + c) * 25 + tap];
        }
        __syncthreads();

        // ================= qkv GEMM (mma, 3-term, B double-buffered + L1 prefetch) =================
        {
            float qacc[4][3][4];
            #pragma unroll
            for (int m = 0; m < 4; ++m)
                #pragma unroll
                for (int j = 0; j < 3; ++j)
                    #pragma unroll
                    for (int q = 0; q < 4; ++q) qacc[m][j][q] = 0.f;

            uint2 bhc[3], blc[3];
            #pragma unroll
            for (int j = 0; j < 3; ++j) {
                int bi = ((head * 24 + warp * 3 + j) * 8 + 0) * 32 + lane;
                bhc[j] = g_qwB_hi[bi];
                blc[j] = g_qwB_lo[bi];
            }
            #pragma unroll
            for (int k = 0; k < 8; ++k) {
                uint2 bhn[3], bln[3];
                if (k < 7) {
                    #pragma unroll
                    for (int j = 0; j < 3; ++j) {
                        int bi = ((head * 24 + warp * 3 + j) * 8 + k + 1) * 32 + lane;
                        bhn[j] = g_qwB_hi[bi];
                        bln[j] = g_qwB_lo[bi];
                        if (k < 6) {
                            pref_l1(&g_qwB_hi[bi + 32]);
                            pref_l1(&g_qwB_lo[bi + 32]);
                        }
                    }
                }
                #pragma unroll
                for (int m = 0; m < 4; ++m) {
                    unsigned Ah[4], Al[4];
                    ldsm_x4(Ah, s2u(&s.ah[(m * 16 + a_r) * FST + k * 16 + a_c]));
                    ldsm_x4(Al, s2u(&s.al[(m * 16 + a_r) * FST + k * 16 + a_c]));
                    #pragma unroll
                    for (int j = 0; j < 3; ++j) {
                        mma16816(qacc[m][j], Ah, reinterpret_cast<const unsigned*>(&bhc[j]));
                        mma16816(qacc[m][j], Ah, reinterpret_cast<const unsigned*>(&blc[j]));
                        mma16816(qacc[m][j], Al, reinterpret_cast<const unsigned*>(&bhc[j]));
                    }
                }
                if (k < 7) {
                    #pragma unroll
                    for (int j = 0; j < 3; ++j) { bhc[j] = bhn[j]; blc[j] = bln[j]; }
                }
            }
            // epilogue: BN fold -> yq (q fp32) | kh/kl | vh/vl
            #pragma unroll
            for (int m = 0; m < 4; ++m) {
                int rb = m * 16 + (lane >> 2);
                #pragma unroll
                for (int j = 0; j < 3; ++j) {
                    int c0 = warp * 24 + j * 8 + (lane & 3) * 2;
                    float sc0 = s.qscale[c0], sc1 = s.qscale[c0 + 1];
                    float bb0 = s.qbias[c0],  bb1 = s.qbias[c0 + 1];
                    #pragma unroll
                    for (int h2 = 0; h2 < 2; ++h2) {
                        int r = rb + h2 * 8;
                        if (r < NTOK) {
                            float y0 = qacc[m][j][h2 * 2 + 0] * sc0 + bb0;
                            float y1 = qacc[m][j][h2 * 2 + 1] * sc1 + bb1;
                            if (c0 < 32) {
                                s.u2.yq[r * YQS + c0]     = y0;
                                s.u2.yq[r * YQS + c0 + 1] = y1;
                            } else if (c0 < 64) {
                                unsigned hp, lp;
                                split2(y0, y1, hp, lp);
                                *reinterpret_cast<unsigned*>(&s.u1.s1.kh[r * KQS + c0 - 32]) = hp;
                                *reinterpret_cast<unsigned*>(&s.u1.s1.kl[r * KQS + c0 - 32]) = lp;
                            } else {
                                unsigned hp, lp;
                                split2(y0, y1, hp, lp);
                                *reinterpret_cast<unsigned*>(&s.vh[r * FST + c0 - 64]) = hp;
                                *reinterpret_cast<unsigned*>(&s.vl[r * FST + c0 - 64]) = lp;
                            }
                        }
                    }
                }
            }
        }
        __syncthreads();

        // ================= depthwise 5x5 conv (+BN) -> qh/ql =================
        for (int idx = t; idx < NTOK * KDIM; idx += 256) {
            int n = idx >> 5, c = idx & 31;
            int r = n / 7, sc_ = n % 7;
            float sum = 0.f;
            #pragma unroll
            for (int a = 0; a < 5; ++a) {
                int rr = r + a - 2;
                if ((unsigned)rr < 7u) {
                    #pragma unroll
                    for (int bb = 0; bb < 5; ++bb) {
                        int ss = sc_ + bb - 2;
                        if ((unsigned)ss < 7u)
                            sum += s.u2.yq[(rr * 7 + ss) * YQS + c] * s.dww[(a * 5 + bb) * 32 + c];
                    }
                }
            }
            float qv = sum * s.dws[c] + s.dwb[c];
            __nv_bfloat16 hv = __float2bfloat16(qv);
            s.u1.s1.qh[n * KQS + c] = hv;
            s.u1.s1.ql[n * KQS + c] = __float2bfloat16(qv - __bfloat162float(hv));
        }
        __syncthreads();

        // ================= qk scores (mma, 3-term) =================
        {
            const int wm = (warp & 3) * 16, wn = (warp >> 2) * 32;
            float sacc[4][4];
            #pragma unroll
            for (int nt = 0; nt < 4; ++nt)
                #pragma unroll
                for (int q = 0; q < 4; ++q) sacc[nt][q] = 0.f;

            #pragma unroll
            for (int k16 = 0; k16 < 2; ++k16) {
                unsigned Ah[4], Al[4];
                ldsm_x4(Ah, s2u(&s.u1.s1.qh[(wm + a_r) * KQS + k16 * 16 + a_c]));
                ldsm_x4(Al, s2u(&s.u1.s1.ql[(wm + a_r) * KQS + k16 * 16 + a_c]));
                unsigned Bh[2][4], Bl[2][4];
                #pragma unroll
                for (int g = 0; g < 2; ++g) {
                    ldsm_x4(Bh[g], s2u(&s.u1.s1.kh[(wn + g * 16 + b_r) * KQS + k16 * 16 + b_c]));
                    ldsm_x4(Bl[g], s2u(&s.u1.s1.kl[(wn + g * 16 + b_r) * KQS + k16 * 16 + b_c]));
                }
                #pragma unroll
                for (int nt = 0; nt < 4; ++nt) {
                    const unsigned* bh = &Bh[nt >> 1][(nt & 1) * 2];
                    const unsigned* bl = &Bl[nt >> 1][(nt & 1) * 2];
                    mma16816(sacc[nt], Ah, bh);
                    mma16816(sacc[nt], Ah, bl);
                    mma16816(sacc[nt], Al, bh);
                }
            }
            const float* abr = s.ab + head * NTOK;
            int r0 = wm + (lane >> 2);
            #pragma unroll
            for (int nt = 0; nt < 4; ++nt) {
                int c0 = wn + nt * 8 + (lane & 3) * 2;
                #pragma unroll
                for (int h2 = 0; h2 < 2; ++h2) {
                    int r = r0 + h2 * 8;
                    if (r < NTOK) {
                        int rr7 = r / 7, rm7 = r % 7;
                        #pragma unroll
                        for (int q = 0; q < 2; ++q) {
                            int c = c0 + q;
                            if (c < NTOK) {
                                int cd = c / 7, cm = c % 7;
                                int bi = abs(rr7 - cd) * 7 + abs(rm7 - cm);
                                s.u2.attn[r * ASF + c] =
                                    sacc[nt][h2 * 2 + q] * scale + abr[bi];
                            }
                        }
                    }
                }
            }
        }
        __syncthreads();

        // ================= softmax -> ath/atl =================
        for (int r = warp; r < NTOK; r += 8) {
            float a = s.u2.attn[r * ASF + lane];
            bool hasb = (lane + 32) < NTOK;
            float bv = hasb ? s.u2.attn[r * ASF + 32 + lane] : -1e30f;
            float mx = fmaxf(a, bv);
            #pragma unroll
            for (int off = 16; off > 0; off >>= 1)
                mx = fmaxf(mx, __shfl_xor_sync(0xffffffffu, mx, off));
            float ea = __expf(a - mx);
            float eb = hasb ? __expf(bv - mx) : 0.f;
            float sm = ea + eb;
            #pragma unroll
            for (int off = 16; off > 0; off >>= 1)
                sm += __shfl_xor_sync(0xffffffffu, sm, off);
            float inv = __frcp_rn(sm);
            float pa = ea * inv, pb = eb * inv;
            __nv_bfloat16 ph = __float2bfloat16(pa);
            s.u1.s2.ath[r * ATS + lane] = ph;
            s.u1.s2.atl[r * ATS + lane] = __float2bfloat16(pa - __bfloat162float(ph));
            if (hasb) {
                __nv_bfloat16 qh2 = __float2bfloat16(pb);
                s.u1.s2.ath[r * ATS + 32 + lane] = qh2;
                s.u1.s2.atl[r * ATS + 32 + lane] = __float2bfloat16(pb - __bfloat162float(qh2));
            }
            if (lane < 15) {
                __nv_bfloat16 z = __float2bfloat16(0.f);
                s.u1.s2.ath[r * ATS + 49 + lane] = z;
                s.u1.s2.atl[r * ATS + 49 + lane] = z;
            }
        }
        __syncthreads();

        // ================= attn @ v (mma, 3-term) =================
        {
            const int wm2 = (warp & 1) * 32, wn2 = (warp >> 1) * 32;
            float facc[2][4][4];
            #pragma unroll
            for (int mt = 0; mt < 2; ++mt)
                #pragma unroll
                for (int nt = 0; nt < 4; ++nt)
                    #pragma unroll
                    for (int q = 0; q < 4; ++q) facc[mt][nt][q] = 0.f;

            #pragma unroll
            for (int k16 = 0; k16 < 4; ++k16) {
                unsigned Ah[2][4], Al[2][4];
                #pragma unroll
                for (int mt = 0; mt < 2; ++mt) {
                    ldsm_x4(Ah[mt], s2u(&s.u1.s2.ath[(wm2 + mt * 16 + a_r) * ATS + k16 * 16 + a_c]));
                    ldsm_x4(Al[mt], s2u(&s.u1.s2.atl[(wm2 + mt * 16 + a_r) * ATS + k16 * 16 + a_c]));
                }
                unsigned Bh[2][4], Bl[2][4];
                #pragma unroll
                for (int g = 0; g < 2; ++g) {
                    unsigned addr_h = s2u(&s.vh[(k16 * 16 + (lane & 15)) * FST +
                                                wn2 + g * 16 + (lane >> 4) * 8]);
                    unsigned addr_l = s2u(&s.vl[(k16 * 16 + (lane & 15)) * FST +
                                                wn2 + g * 16 + (lane >> 4) * 8]);
                    ldsm_x4_t(Bh[g], addr_h);
                    ldsm_x4_t(Bl[g], addr_l);
                }
                #pragma unroll
                for (int mt = 0; mt < 2; ++mt)
                    #pragma unroll
                    for (int nt = 0; nt < 4; ++nt) {
                        const unsigned* bh = &Bh[nt >> 1][(nt & 1) * 2];
                        const unsigned* bl = &Bl[nt >> 1][(nt & 1) * 2];
                        mma16816(facc[mt][nt], Ah[mt], bh);
                        mma16816(facc[mt][nt], Ah[mt], bl);
                        mma16816(facc[mt][nt], Al[mt], bh);
                    }
            }
            // epilogue: new feat (ah/al) + relu to g_hA
            #pragma unroll
            for (int mt = 0; mt < 2; ++mt)
                #pragma unroll
                for (int nt = 0; nt < 4; ++nt) {
                    int c0 = wn2 + nt * 8 + (lane & 3) * 2;
                    int C  = head * 128 + c0;
                    int kstep = C >> 4, jj = C & 15;
                    int quad = (jj < 8) ? (jj >> 1) : ((jj - 8) >> 1);
                    int word = (jj < 8) ? 0 : 1;
                    #pragma unroll
                    for (int h2 = 0; h2 < 2; ++h2) {
                        int r = wm2 + mt * 16 + (lane >> 2) + h2 * 8;
                        if (r < NTOK) {
                            float v0 = facc[mt][nt][h2 * 2 + 0];
                            float v1 = facc[mt][nt][h2 * 2 + 1];
                            unsigned hp, lp;
                            split2(v0, v1, hp, lp);
                            *reinterpret_cast<unsigned*>(&s.ah[r * FST + c0]) = hp;
                            *reinterpret_cast<unsigned*>(&s.al[r * FST + c0]) = lp;
                            float r0v = fmaxf(v0, 0.f), r1v = fmaxf(v1, 0.f);
                            unsigned ghp, glp;
                            split2(r0v, r1v, ghp, glp);
                            size_t row = (size_t)b * NTOK + r;
                            size_t idx = (row >> 4) * 2048 + (size_t)kstep * 64 +
                                         (row & 15) * 4 + quad;
                            unsigned* up = reinterpret_cast<unsigned*>(&g_hA[idx]);
                            up[word]     = ghp;
                            up[word + 2] = glp;
                        }
                    }
                }
        }
        if (head < NHEADS - 1 && t < 196)
            pref_l1(&x[xoff + (t >> 2) * CH + (head + 1) * 128 + (t & 3) * 32]);
        __syncthreads();
    }
}

// ==================== Phase B: projection — pure LDG + mma, L1-prefetch pipelined ====================

__global__ void __launch_bounds__(256, 2) proj_mma_kernel(
    const float* __restrict__ proj_g, const float* __restrict__ proj_b,
    const float* __restrict__ proj_m, const float* __restrict__ proj_v,
    float* __restrict__ out)
{
    __shared__ float sPs[64], sPb[64];

    const int t = threadIdx.x, lane = t & 31, warp = t >> 5;
    const int row0 = blockIdx.y * 128, col0 = blockIdx.x * 64;

    if (t < 64) {
        int o = col0 + t;
        float sc = proj_g[o] * rsqrtf(proj_v[o] + EPS);
        sPs[t] = sc;
        sPb[t] = proj_b[o] - proj_m[o] * sc;
    }
    __syncthreads();

    const int wm = (warp >> 1) * 32, wn = (warp & 1) * 32;
    const int nb = (col0 >> 3) + (wn >> 3);

    float acc[2][4][4];
    #pragma unroll
    for (int mt = 0; mt < 2; ++mt)
        #pragma unroll
        for (int nt = 0; nt < 4; ++nt)
            #pragma unroll
            for (int q = 0; q < 4; ++q) acc[mt][nt][q] = 0.f;

    const int tile0 = (row0 + wm) >> 4;

    // warm the L1 for the first two k-steps (prefetch distance 2)
    #pragma unroll
    for (int p = 0; p < 2; ++p) {
        #pragma unroll
        for (int mt = 0; mt < 2; ++mt) {
            size_t base = (size_t)(tile0 + mt) * 2048 + p * 64;
            pref_l1(&g_hA[base + lane]);
            pref_l1(&g_hA[base + 32 + lane]);
        }
        #pragma unroll
        for (int nt = 0; nt < 4; ++nt)
            pref_l1(&g_wB[((nb + nt) * 32 + p) * 32 + lane]);
    }

    for (int ks = 0; ks < 32; ++ks) {
        unsigned Ah[2][4], Al[2][4];
        #pragma unroll
        for (int mt = 0; mt < 2; ++mt) {
            size_t base = (size_t)(tile0 + mt) * 2048 + ks * 64;
            uint4 U0 = g_hA[base + lane];
            uint4 U1 = g_hA[base + 32 + lane];
            Ah[mt][0] = U0.x; Ah[mt][1] = U1.x; Ah[mt][2] = U0.y; Ah[mt][3] = U1.y;
            Al[mt][0] = U0.z; Al[mt][1] = U1.z; Al[mt][2] = U0.w; Al[mt][3] = U1.w;
        }
        uint4 W[4];
        #pragma unroll
        for (int nt = 0; nt < 4; ++nt)
            W[nt] = g_wB[((nb + nt) * 32 + ks) * 32 + lane];

        // prefetch ks+2 (no register cost)
        if (ks < 30) {
            #pragma unroll
            for (int mt = 0; mt < 2; ++mt) {
                size_t base = (size_t)(tile0 + mt) * 2048 + (ks + 2) * 64;
                pref_l1(&g_hA[base + lane]);
                pref_l1(&g_hA[base + 32 + lane]);
            }
            #pragma unroll
            for (int nt = 0; nt < 4; ++nt)
                pref_l1(&g_wB[((nb + nt) * 32 + ks + 2) * 32 + lane]);
        }

        #pragma unroll
        for (int mt = 0; mt < 2; ++mt)
            #pragma unroll
            for (int nt = 0; nt < 4; ++nt) {
                unsigned bh[2] = {W[nt].x, W[nt].y};
                unsigned bl[2] = {W[nt].z, W[nt].w};
                mma16816(acc[mt][nt], Ah[mt], bh);
                mma16816(acc[mt][nt], Ah[mt], bl);
                mma16816(acc[mt][nt], Al[mt], bh);
            }
    }

    const int er = lane >> 2, ec = (lane & 3) * 2;
    #pragma unroll
    for (int mt = 0; mt < 2; ++mt)
        #pragma unroll
        for (int nt = 0; nt < 4; ++nt) {
            int cl = wn + nt * 8 + ec;
            float s0 = sPs[cl], s1 = sPs[cl + 1];
            float b0 = sPb[cl], b1 = sPb[cl + 1];
            size_t gr = (size_t)(row0 + wm + mt * 16 + er) * 512 + col0 + cl;
            *reinterpret_cast<float2*>(&out[gr]) =
                make_float2(acc[mt][nt][0] * s0 + b0, acc[mt][nt][1] * s1 + b1);
            *reinterpret_cast<float2*>(&out[gr + (size_t)8 * 512]) =
                make_float2(acc[mt][nt][2] * s0 + b0, acc[mt][nt][3] * s1 + b1);
        }
}

// ==================== launch ====================

extern "C" void kernel_launch(void* const* d_in, const int* in_sizes, int n_in,
                              void* d_out, int out_size) {
    const float* x         = (const float*)d_in[0];
    const float* qkv_w     = (const float*)d_in[1];
    const float* qkv_g     = (const float*)d_in[2];
    const float* qkv_b     = (const float*)d_in[3];
    const float* qkv_m     = (const float*)d_in[4];
    const float* qkv_v     = (const float*)d_in[5];
    const float* dw_w      = (const float*)d_in[6];
    const float* dw_g      = (const float*)d_in[7];
    const float* dw_b      = (const float*)d_in[8];
    const float* dw_m      = (const float*)d_in[9];
    const float* dw_v      = (const float*)d_in[10];
    const float* proj_w    = (const float*)d_in[11];
    const float* proj_g    = (const float*)d_in[12];
    const float* proj_b    = (const float*)d_in[13];
    const float* proj_m    = (const float*)d_in[14];
    const float* proj_v    = (const float*)d_in[15];
    const float* attn_bias = (const float*)d_in[16];
    float* out = (float*)d_out;

    cudaFuncSetAttribute(cascade_kernel,
                         cudaFuncAttributeMaxDynamicSharedMemorySize,
                         (int)sizeof(SmemA));

    wsplit_kernel<<<256, 256>>>(proj_w);
    qkvsplit_kernel<<<192, 256>>>(qkv_w);

    cascade_kernel<<<BATCH, 256, sizeof(SmemA)>>>(
        x, qkv_g, qkv_b, qkv_m, qkv_v,
        dw_w, dw_g, dw_b, dw_m, dw_v, attn_bias);

    proj_mma_kernel<<<dim3(8, 784), 256>>>(proj_g, proj_b, proj_m, proj_v, out);
}

// round 8
// speedup vs baseline: 1.1853x; 1.1853x over previous
#include <cuda_runtime.h>
#include <cuda_bf16.h>
#include <cuda_fp16.h>

#define BATCH   2048
#define NTOK    49
#define CH      512
#define NHEADS  4
#define KDIM    32
#define DV      128
#define QO      192
#define EPS     1e-5f
#define FST     136      // feat / v row stride (bf16)
#define KQS     40       // k / q row stride (bf16)
#define ATS     72       // attn-prob row stride (bf16)
#define ASF     52       // attn fp32 score row stride
#define YQS     36       // conv-input fp32 stride
#define NROWS   ((size_t)BATCH * NTOK)   // 100352

// -------- global scratch --------
// h in proj-A-fragment tiled layout (fp16 hi/lo): [m16tile][kstep(32)][r16(16)][quad(4)] uint4
//   uint4 = {hi(c,c+1), hi(c+8,c+9), lo(c,c+1), lo(c+8,c+9)}
__device__ __align__(16) uint4 g_hA[NROWS * 128];
// proj weights fp16 (hi only), B-fragment permuted: [n8(64)][k16(32)][lane(32)] uint2
__device__ __align__(16) uint2 g_wBh[64 * 32 * 32];
// qkv weights bf16 hi/lo, B-fragment permuted: [head][j(24)][kstep(8)][lane(32)] uint2
__device__ __align__(16) uint2 g_qwB_hi[NHEADS * 24 * 8 * 32];
__device__ __align__(16) uint2 g_qwB_lo[NHEADS * 24 * 8 * 32];

// ==================== helpers ====================
__device__ __forceinline__ unsigned s2u(const void* p) {
    return (unsigned)__cvta_generic_to_shared(p);
}
__device__ __forceinline__ void ldsm_x4(unsigned* r, unsigned addr) {
    asm volatile("ldmatrix.sync.aligned.m8n8.x4.shared.b16 {%0,%1,%2,%3}, [%4];"
        : "=r"(r[0]), "=r"(r[1]), "=r"(r[2]), "=r"(r[3]) : "r"(addr));
}
__device__ __forceinline__ void ldsm_x4_t(unsigned* r, unsigned addr) {
    asm volatile("ldmatrix.sync.aligned.m8n8.x4.trans.shared.b16 {%0,%1,%2,%3}, [%4];"
        : "=r"(r[0]), "=r"(r[1]), "=r"(r[2]), "=r"(r[3]) : "r"(addr));
}
// bf16 mma
__device__ __forceinline__ void mma16816(float* c, const unsigned* a, const unsigned* b) {
    asm volatile("mma.sync.aligned.m16n8k16.row.col.f32.bf16.bf16.f32 "
        "{%0,%1,%2,%3}, {%4,%5,%6,%7}, {%8,%9}, {%0,%1,%2,%3};"
        : "+f"(c[0]), "+f"(c[1]), "+f"(c[2]), "+f"(c[3])
        : "r"(a[0]), "r"(a[1]), "r"(a[2]), "r"(a[3]), "r"(b[0]), "r"(b[1]));
}
// fp16 mma
__device__ __forceinline__ void mma16816h(float* c, const unsigned* a, const unsigned* b) {
    asm volatile("mma.sync.aligned.m16n8k16.row.col.f32.f16.f16.f32 "
        "{%0,%1,%2,%3}, {%4,%5,%6,%7}, {%8,%9}, {%0,%1,%2,%3};"
        : "+f"(c[0]), "+f"(c[1]), "+f"(c[2]), "+f"(c[3])
        : "r"(a[0]), "r"(a[1]), "r"(a[2]), "r"(a[3]), "r"(b[0]), "r"(b[1]));
}
__device__ __forceinline__ unsigned packbf2(float a, float b) {
    __nv_bfloat162 p = __halves2bfloat162(__float2bfloat16(a), __float2bfloat16(b));
    return *reinterpret_cast<unsigned*>(&p);
}
__device__ __forceinline__ void split2(float v0, float v1, unsigned& hp, unsigned& lp) {
    __nv_bfloat16 h0 = __float2bfloat16(v0), h1 = __float2bfloat16(v1);
    hp = (unsigned)__bfloat16_as_ushort(h0) | ((unsigned)__bfloat16_as_ushort(h1) << 16);
    lp = packbf2(v0 - __bfloat162float(h0), v1 - __bfloat162float(h1));
}
__device__ __forceinline__ unsigned packh2(__half a, __half b) {
    __half2 p = __halves2half2(a, b);
    return *reinterpret_cast<unsigned*>(&p);
}
// fp16 hi/lo split of 2 floats
__device__ __forceinline__ void split2h(float v0, float v1, unsigned& hp, unsigned& lp) {
    __half h0 = __float2half_rn(v0), h1 = __float2half_rn(v1);
    __half l0 = __float2half_rn(v0 - __half2float(h0));
    __half l1 = __float2half_rn(v1 - __half2float(h1));
    hp = packh2(h0, h1);
    lp = packh2(l0, l1);
}
__device__ __forceinline__ void pref_l1(const void* p) {
    asm volatile("prefetch.global.L1 [%0];" :: "l"(p));
}

// ==================== prep kernels ====================
__global__ void wsplit_kernel(const float* __restrict__ w) {
    int i = blockIdx.x * 256 + threadIdx.x;       // 65536
    int j0 = i >> 10;
    int s_ = (i >> 5) & 31;
    int l  = i & 31;
    int n  = j0 * 8 + (l >> 2);
    int k0 = s_ * 16 + (l & 3) * 2;
    float a0 = w[n * 512 + k0],     a1 = w[n * 512 + k0 + 1];
    float a2 = w[n * 512 + k0 + 8], a3 = w[n * 512 + k0 + 9];
    uint2 p;
    p.x = packh2(__float2half_rn(a0), __float2half_rn(a1));
    p.y = packh2(__float2half_rn(a2), __float2half_rn(a3));
    g_wBh[i] = p;
}

__global__ void qkvsplit_kernel(const float* __restrict__ w) {
    int i = blockIdx.x * 256 + threadIdx.x;       // 49152
    int h = i / (192 * 64);
    int rem = i % (192 * 64);
    int n = rem / 64;
    int p = rem % 64;
    float v0 = w[((size_t)h * 192 + n) * 128 + p * 2];
    float v1 = w[((size_t)h * 192 + n) * 128 + p * 2 + 1];
    unsigned hi, lo;
    split2(v0, v1, hi, lo);
    int j = n >> 3, kstep = p >> 3, q = p & 7;
    int r = q >> 2, lm4 = q & 3;
    int lane = (n & 7) * 4 + lm4;
    int base = ((h * 24 + j) * 8 + kstep) * 32 + lane;
    reinterpret_cast<unsigned*>(g_qwB_hi)[base * 2 + r] = hi;
    reinterpret_cast<unsigned*>(g_qwB_lo)[base * 2 + r] = lo;
}

// ==================== Phase A: cascaded heads (all-mma, bf16 3-term) ====================

struct __align__(16) SmemA {
    __nv_bfloat16 ah[64 * FST], al[64 * FST];
    __nv_bfloat16 vh[64 * FST], vl[64 * FST];
    union U1 {
        struct { __nv_bfloat16 kh[64 * KQS], kl[64 * KQS],
                               qh[64 * KQS], ql[64 * KQS]; } s1;
        struct { __nv_bfloat16 ath[64 * ATS], atl[64 * ATS]; } s2;
    } u1;
    union U2 { float attn[49 * ASF]; float yq[49 * YQS]; } u2;
    float dww[25 * 32];
    float qscale[QO], qbias[QO];
    float dws[KDIM], dwb[KDIM];
    float ab[NHEADS * NTOK];
};

__global__ void __launch_bounds__(256, 2) cascade_kernel(
    const float* __restrict__ x,
    const float* __restrict__ qkv_g,  const float* __restrict__ qkv_b,
    const float* __restrict__ qkv_m,  const float* __restrict__ qkv_v,
    const float* __restrict__ dw_w,   const float* __restrict__ dw_g,
    const float* __restrict__ dw_b,   const float* __restrict__ dw_m,
    const float* __restrict__ dw_v,   const float* __restrict__ attn_bias)
{
    extern __shared__ unsigned char smem_raw[];
    SmemA& s = *reinterpret_cast<SmemA*>(smem_raw);
    const int t    = threadIdx.x;
    const int b    = blockIdx.x;
    const int lane = t & 31;
    const int warp = t >> 5;
    const float scale = rsqrtf((float)KDIM);
    const size_t xoff = (size_t)b * NTOK * CH;

    for (int j = t; j < NHEADS * NTOK; j += 256) s.ab[j] = attn_bias[j];
    for (int j = t; j < 15 * FST; j += 256) {
        __nv_bfloat16 z = __float2bfloat16(0.f);
        s.ah[49 * FST + j] = z; s.al[49 * FST + j] = z;
        s.vh[49 * FST + j] = z; s.vl[49 * FST + j] = z;
    }
    if (t < 196) pref_l1(&x[xoff + (t >> 2) * CH + (t & 3) * 32]);

    const int a_r = lane & 15, a_c = (lane >> 4) * 8;
    const int b_r = (lane & 7) + ((lane & 16) ? 8 : 0);
    const int b_c = (lane & 8) ? 8 : 0;

    for (int head = 0; head < NHEADS; ++head) {
        // ---- feat update + hi/lo split ----
        for (int jdx = t; jdx < NTOK * 128; jdx += 256) {
            int n = jdx >> 7, d = jdx & 127;
            float v;
            if (head == 0) {
                v = x[xoff + n * CH + d];
            } else {
                v = __bfloat162float(s.ah[n * FST + d]) +
                    __bfloat162float(s.al[n * FST + d]) +
                    x[xoff + n * CH + head * 128 + d];
            }
            __nv_bfloat16 hv = __float2bfloat16(v);
            s.ah[n * FST + d] = hv;
            s.al[n * FST + d] = __float2bfloat16(v - __bfloat162float(hv));
        }
        // ---- BN folds ----
        if (t < QO) {
            float sc = qkv_g[head * QO + t] * rsqrtf(qkv_v[head * QO + t] + EPS);
            s.qscale[t] = sc;
            s.qbias[t]  = qkv_b[head * QO + t] - qkv_m[head * QO + t] * sc;
        } else if (t < QO + KDIM) {
            int c = t - QO;
            float sc = dw_g[head * KDIM + c] * rsqrtf(dw_v[head * KDIM + c] + EPS);
            s.dws[c] = sc;
            s.dwb[c] = dw_b[head * KDIM + c] - dw_m[head * KDIM + c] * sc;
        }
        for (int j = t; j < KDIM * 25; j += 256) {
            int c = j / 25, tap = j % 25;
            s.dww[tap * 32 + c] = dw_w[(head * KDIM + c) * 25 + tap];
        }
        __syncthreads();

        // ================= qkv GEMM (mma, 3-term, B double-buffered) =================
        {
            float qacc[4][3][4];
            #pragma unroll
            for (int m = 0; m < 4; ++m)
                #pragma unroll
                for (int j = 0; j < 3; ++j)
                    #pragma unroll
                    for (int q = 0; q < 4; ++q) qacc[m][j][q] = 0.f;

            uint2 bhc[3], blc[3];
            #pragma unroll
            for (int j = 0; j < 3; ++j) {
                int bi = ((head * 24 + warp * 3 + j) * 8 + 0) * 32 + lane;
                bhc[j] = g_qwB_hi[bi];
                blc[j] = g_qwB_lo[bi];
            }
            #pragma unroll
            for (int k = 0; k < 8; ++k) {
                uint2 bhn[3], bln[3];
                if (k < 7) {
                    #pragma unroll
                    for (int j = 0; j < 3; ++j) {
                        int bi = ((head * 24 + warp * 3 + j) * 8 + k + 1) * 32 + lane;
                        bhn[j] = g_qwB_hi[bi];
                        bln[j] = g_qwB_lo[bi];
                    }
                }
                #pragma unroll
                for (int m = 0; m < 4; ++m) {
                    unsigned Ah[4], Al[4];
                    ldsm_x4(Ah, s2u(&s.ah[(m * 16 + a_r) * FST + k * 16 + a_c]));
                    ldsm_x4(Al, s2u(&s.al[(m * 16 + a_r) * FST + k * 16 + a_c]));
                    #pragma unroll
                    for (int j = 0; j < 3; ++j) {
                        mma16816(qacc[m][j], Ah, reinterpret_cast<const unsigned*>(&bhc[j]));
                        mma16816(qacc[m][j], Ah, reinterpret_cast<const unsigned*>(&blc[j]));
                        mma16816(qacc[m][j], Al, reinterpret_cast<const unsigned*>(&bhc[j]));
                    }
                }
                if (k < 7) {
                    #pragma unroll
                    for (int j = 0; j < 3; ++j) { bhc[j] = bhn[j]; blc[j] = bln[j]; }
                }
            }
            // epilogue: BN fold -> yq (q fp32) | kh/kl | vh/vl
            #pragma unroll
            for (int m = 0; m < 4; ++m) {
                int rb = m * 16 + (lane >> 2);
                #pragma unroll
                for (int j = 0; j < 3; ++j) {
                    int c0 = warp * 24 + j * 8 + (lane & 3) * 2;
                    float sc0 = s.qscale[c0], sc1 = s.qscale[c0 + 1];
                    float bb0 = s.qbias[c0],  bb1 = s.qbias[c0 + 1];
                    #pragma unroll
                    for (int h2 = 0; h2 < 2; ++h2) {
                        int r = rb + h2 * 8;
                        if (r < NTOK) {
                            float y0 = qacc[m][j][h2 * 2 + 0] * sc0 + bb0;
                            float y1 = qacc[m][j][h2 * 2 + 1] * sc1 + bb1;
                            if (c0 < 32) {
                                s.u2.yq[r * YQS + c0]     = y0;
                                s.u2.yq[r * YQS + c0 + 1] = y1;
                            } else if (c0 < 64) {
                                unsigned hp, lp;
                                split2(y0, y1, hp, lp);
                                *reinterpret_cast<unsigned*>(&s.u1.s1.kh[r * KQS + c0 - 32]) = hp;
                                *reinterpret_cast<unsigned*>(&s.u1.s1.kl[r * KQS + c0 - 32]) = lp;
                            } else {
                                unsigned hp, lp;
                                split2(y0, y1, hp, lp);
                                *reinterpret_cast<unsigned*>(&s.vh[r * FST + c0 - 64]) = hp;
                                *reinterpret_cast<unsigned*>(&s.vl[r * FST + c0 - 64]) = lp;
                            }
                        }
                    }
                }
            }
        }
        __syncthreads();

        // ================= depthwise 5x5 conv (+BN) -> qh/ql =================
        for (int idx = t; idx < NTOK * KDIM; idx += 256) {
            int n = idx >> 5, c = idx & 31;
            int r = n / 7, sc_ = n % 7;
            float sum = 0.f;
            #pragma unroll
            for (int a = 0; a < 5; ++a) {
                int rr = r + a - 2;
                if ((unsigned)rr < 7u) {
                    #pragma unroll
                    for (int bb = 0; bb < 5; ++bb) {
                        int ss = sc_ + bb - 2;
                        if ((unsigned)ss < 7u)
                            sum += s.u2.yq[(rr * 7 + ss) * YQS + c] * s.dww[(a * 5 + bb) * 32 + c];
                    }
                }
            }
            float qv = sum * s.dws[c] + s.dwb[c];
            __nv_bfloat16 hv = __float2bfloat16(qv);
            s.u1.s1.qh[n * KQS + c] = hv;
            s.u1.s1.ql[n * KQS + c] = __float2bfloat16(qv - __bfloat162float(hv));
        }
        __syncthreads();

        // ================= qk scores (mma, 3-term) =================
        {
            const int wm = (warp & 3) * 16, wn = (warp >> 2) * 32;
            float sacc[4][4];
            #pragma unroll
            for (int nt = 0; nt < 4; ++nt)
                #pragma unroll
                for (int q = 0; q < 4; ++q) sacc[nt][q] = 0.f;

            #pragma unroll
            for (int k16 = 0; k16 < 2; ++k16) {
                unsigned Ah[4], Al[4];
                ldsm_x4(Ah, s2u(&s.u1.s1.qh[(wm + a_r) * KQS + k16 * 16 + a_c]));
                ldsm_x4(Al, s2u(&s.u1.s1.ql[(wm + a_r) * KQS + k16 * 16 + a_c]));
                unsigned Bh[2][4], Bl[2][4];
                #pragma unroll
                for (int g = 0; g < 2; ++g) {
                    ldsm_x4(Bh[g], s2u(&s.u1.s1.kh[(wn + g * 16 + b_r) * KQS + k16 * 16 + b_c]));
                    ldsm_x4(Bl[g], s2u(&s.u1.s1.kl[(wn + g * 16 + b_r) * KQS + k16 * 16 + b_c]));
                }
                #pragma unroll
                for (int nt = 0; nt < 4; ++nt) {
                    const unsigned* bh = &Bh[nt >> 1][(nt & 1) * 2];
                    const unsigned* bl = &Bl[nt >> 1][(nt & 1) * 2];
                    mma16816(sacc[nt], Ah, bh);
                    mma16816(sacc[nt], Ah, bl);
                    mma16816(sacc[nt], Al, bh);
                }
            }
            const float* abr = s.ab + head * NTOK;
            int r0 = wm + (lane >> 2);
            #pragma unroll
            for (int nt = 0; nt < 4; ++nt) {
                int c0 = wn + nt * 8 + (lane & 3) * 2;
                #pragma unroll
                for (int h2 = 0; h2 < 2; ++h2) {
                    int r = r0 + h2 * 8;
                    if (r < NTOK) {
                        int rr7 = r / 7, rm7 = r % 7;
                        #pragma unroll
                        for (int q = 0; q < 2; ++q) {
                            int c = c0 + q;
                            if (c < NTOK) {
                                int cd = c / 7, cm = c % 7;
                                int bi = abs(rr7 - cd) * 7 + abs(rm7 - cm);
                                s.u2.attn[r * ASF + c] =
                                    sacc[nt][h2 * 2 + q] * scale + abr[bi];
                            }
                        }
                    }
                }
            }
        }
        __syncthreads();

        // ================= softmax -> ath/atl =================
        for (int r = warp; r < NTOK; r += 8) {
            float a = s.u2.attn[r * ASF + lane];
            bool hasb = (lane + 32) < NTOK;
            float bv = hasb ? s.u2.attn[r * ASF + 32 + lane] : -1e30f;
            float mx = fmaxf(a, bv);
            #pragma unroll
            for (int off = 16; off > 0; off >>= 1)
                mx = fmaxf(mx, __shfl_xor_sync(0xffffffffu, mx, off));
            float ea = __expf(a - mx);
            float eb = hasb ? __expf(bv - mx) : 0.f;
            float sm = ea + eb;
            #pragma unroll
            for (int off = 16; off > 0; off >>= 1)
                sm += __shfl_xor_sync(0xffffffffu, sm, off);
            float inv = __frcp_rn(sm);
            float pa = ea * inv, pb = eb * inv;
            __nv_bfloat16 ph = __float2bfloat16(pa);
            s.u1.s2.ath[r * ATS + lane] = ph;
            s.u1.s2.atl[r * ATS + lane] = __float2bfloat16(pa - __bfloat162float(ph));
            if (hasb) {
                __nv_bfloat16 qh2 = __float2bfloat16(pb);
                s.u1.s2.ath[r * ATS + 32 + lane] = qh2;
                s.u1.s2.atl[r * ATS + 32 + lane] = __float2bfloat16(pb - __bfloat162float(qh2));
            }
            if (lane < 15) {
                __nv_bfloat16 z = __float2bfloat16(0.f);
                s.u1.s2.ath[r * ATS + 49 + lane] = z;
                s.u1.s2.atl[r * ATS + 49 + lane] = z;
            }
        }
        __syncthreads();

        // ================= attn @ v (mma, 3-term) =================
        {
            const int wm2 = (warp & 1) * 32, wn2 = (warp >> 1) * 32;
            float facc[2][4][4];
            #pragma unroll
            for (int mt = 0; mt < 2; ++mt)
                #pragma unroll
                for (int nt = 0; nt < 4; ++nt)
                    #pragma unroll
                    for (int q = 0; q < 4; ++q) facc[mt][nt][q] = 0.f;

            #pragma unroll
            for (int k16 = 0; k16 < 4; ++k16) {
                unsigned Ah[2][4], Al[2][4];
                #pragma unroll
                for (int mt = 0; mt < 2; ++mt) {
                    ldsm_x4(Ah[mt], s2u(&s.u1.s2.ath[(wm2 + mt * 16 + a_r) * ATS + k16 * 16 + a_c]));
                    ldsm_x4(Al[mt], s2u(&s.u1.s2.atl[(wm2 + mt * 16 + a_r) * ATS + k16 * 16 + a_c]));
                }
                unsigned Bh[2][4], Bl[2][4];
                #pragma unroll
                for (int g = 0; g < 2; ++g) {
                    unsigned addr_h = s2u(&s.vh[(k16 * 16 + (lane & 15)) * FST +
                                                wn2 + g * 16 + (lane >> 4) * 8]);
                    unsigned addr_l = s2u(&s.vl[(k16 * 16 + (lane & 15)) * FST +
                                                wn2 + g * 16 + (lane >> 4) * 8]);
                    ldsm_x4_t(Bh[g], addr_h);
                    ldsm_x4_t(Bl[g], addr_l);
                }
                #pragma unroll
                for (int mt = 0; mt < 2; ++mt)
                    #pragma unroll
                    for (int nt = 0; nt < 4; ++nt) {
                        const unsigned* bh = &Bh[nt >> 1][(nt & 1) * 2];
                        const unsigned* bl = &Bl[nt >> 1][(nt & 1) * 2];
                        mma16816(facc[mt][nt], Ah[mt], bh);
                        mma16816(facc[mt][nt], Ah[mt], bl);
                        mma16816(facc[mt][nt], Al[mt], bh);
                    }
            }
            // epilogue: new feat (ah/al bf16) + relu to g_hA (fp16 hi/lo, tiled A layout)
            #pragma unroll
            for (int mt = 0; mt < 2; ++mt)
                #pragma unroll
                for (int nt = 0; nt < 4; ++nt) {
                    int c0 = wn2 + nt * 8 + (lane & 3) * 2;
                    int C  = head * 128 + c0;
                    int kstep = C >> 4, jj = C & 15;
                    int quad = (jj < 8) ? (jj >> 1) : ((jj - 8) >> 1);
                    int word = (jj < 8) ? 0 : 1;
                    #pragma unroll
                    for (int h2 = 0; h2 < 2; ++h2) {
                        int r = wm2 + mt * 16 + (lane >> 2) + h2 * 8;
                        if (r < NTOK) {
                            float v0 = facc[mt][nt][h2 * 2 + 0];
                            float v1 = facc[mt][nt][h2 * 2 + 1];
                            unsigned hp, lp;
                            split2(v0, v1, hp, lp);
                            *reinterpret_cast<unsigned*>(&s.ah[r * FST + c0]) = hp;
                            *reinterpret_cast<unsigned*>(&s.al[r * FST + c0]) = lp;
                            float r0v = fmaxf(v0, 0.f), r1v = fmaxf(v1, 0.f);
                            unsigned ghp, glp;
                            split2h(r0v, r1v, ghp, glp);
                            size_t row = (size_t)b * NTOK + r;
                            size_t idx = (row >> 4) * 2048 + (size_t)kstep * 64 +
                                         (row & 15) * 4 + quad;
                            unsigned* up = reinterpret_cast<unsigned*>(&g_hA[idx]);
                            up[word]     = ghp;
                            up[word + 2] = glp;
                        }
                    }
                }
        }
        if (head < NHEADS - 1 && t < 196)
            pref_l1(&x[xoff + (t >> 2) * CH + (head + 1) * 128 + (t & 3) * 32]);
        __syncthreads();
    }
}

// ==================== Phase B: projection — fp16, 2-term, pure LDG + mma ====================

__global__ void __launch_bounds__(256, 2) proj_mma_kernel(
    const float* __restrict__ proj_g, const float* __restrict__ proj_b,
    const float* __restrict__ proj_m, const float* __restrict__ proj_v,
    float* __restrict__ out)
{
    __shared__ float sPs[64], sPb[64];

    const int t = threadIdx.x, lane = t & 31, warp = t >> 5;
    const int row0 = blockIdx.y * 128, col0 = blockIdx.x * 64;

    if (t < 64) {
        int o = col0 + t;
        float sc = proj_g[o] * rsqrtf(proj_v[o] + EPS);
        sPs[t] = sc;
        sPb[t] = proj_b[o] - proj_m[o] * sc;
    }
    __syncthreads();

    const int wm = (warp >> 1) * 32, wn = (warp & 1) * 32;
    const int nb = (col0 >> 3) + (wn >> 3);

    float acc[2][4][4];
    #pragma unroll
    for (int mt = 0; mt < 2; ++mt)
        #pragma unroll
        for (int nt = 0; nt < 4; ++nt)
            #pragma unroll
            for (int q = 0; q < 4; ++q) acc[mt][nt][q] = 0.f;

    const int tile0 = (row0 + wm) >> 4;

    for (int ks = 0; ks < 32; ++ks) {
        unsigned Ah[2][4], Al[2][4];
        #pragma unroll
        for (int mt = 0; mt < 2; ++mt) {
            size_t base = (size_t)(tile0 + mt) * 2048 + ks * 64;
            uint4 U0 = g_hA[base + lane];
            uint4 U1 = g_hA[base + 32 + lane];
            Ah[mt][0] = U0.x; Ah[mt][1] = U1.x; Ah[mt][2] = U0.y; Ah[mt][3] = U1.y;
            Al[mt][0] = U0.z; Al[mt][1] = U1.z; Al[mt][2] = U0.w; Al[mt][3] = U1.w;
        }
        uint2 W[4];
        #pragma unroll
        for (int nt = 0; nt < 4; ++nt)
            W[nt] = g_wBh[((nb + nt) * 32 + ks) * 32 + lane];

        #pragma unroll
        for (int mt = 0; mt < 2; ++mt)
            #pragma unroll
            for (int nt = 0; nt < 4; ++nt) {
                const unsigned* bw = reinterpret_cast<const unsigned*>(&W[nt]);
                mma16816h(acc[mt][nt], Ah[mt], bw);
                mma16816h(acc[mt][nt], Al[mt], bw);
            }
    }

    const int er = lane >> 2, ec = (lane & 3) * 2;
    #pragma unroll
    for (int mt = 0; mt < 2; ++mt)
        #pragma unroll
        for (int nt = 0; nt < 4; ++nt) {
            int cl = wn + nt * 8 + ec;
            float s0 = sPs[cl], s1 = sPs[cl + 1];
            float b0 = sPb[cl], b1 = sPb[cl + 1];
            size_t gr = (size_t)(row0 + wm + mt * 16 + er) * 512 + col0 + cl;
            *reinterpret_cast<float2*>(&out[gr]) =
                make_float2(acc[mt][nt][0] * s0 + b0, acc[mt][nt][1] * s1 + b1);
            *reinterpret_cast<float2*>(&out[gr + (size_t)8 * 512]) =
                make_float2(acc[mt][nt][2] * s0 + b0, acc[mt][nt][3] * s1 + b1);
        }
}

// ==================== launch ====================

extern "C" void kernel_launch(void* const* d_in, const int* in_sizes, int n_in,
                              void* d_out, int out_size) {
    const float* x         = (const float*)d_in[0];
    const float* qkv_w     = (const float*)d_in[1];
    const float* qkv_g     = (const float*)d_in[2];
    const float* qkv_b     = (const float*)d_in[3];
    const float* qkv_m     = (const float*)d_in[4];
    const float* qkv_v     = (const float*)d_in[5];
    const float* dw_w      = (const float*)d_in[6];
    const float* dw_g      = (const float*)d_in[7];
    const float* dw_b      = (const float*)d_in[8];
    const float* dw_m      = (const float*)d_in[9];
    const float* dw_v      = (const float*)d_in[10];
    const float* proj_w    = (const float*)d_in[11];
    const float* proj_g    = (const float*)d_in[12];
    const float* proj_b    = (const float*)d_in[13];
    const float* proj_m    = (const float*)d_in[14];
    const float* proj_v    = (const float*)d_in[15];
    const float* attn_bias = (const float*)d_in[16];
    float* out = (float*)d_out;

    cudaFuncSetAttribute(cascade_kernel,
                         cudaFuncAttributeMaxDynamicSharedMemorySize,
                         (int)sizeof(SmemA));

    wsplit_kernel<<<256, 256>>>(proj_w);
    qkvsplit_kernel<<<192, 256>>>(qkv_w);

    cascade_kernel<<<BATCH, 256, sizeof(SmemA)>>>(
        x, qkv_g, qkv_b, qkv_m, qkv_v,
        dw_w, dw_g, dw_b, dw_m, dw_v, attn_bias);

    proj_mma_kernel<<<dim3(8, 784), 256>>>(proj_g, proj_b, proj_m, proj_v, out);
}

// round 9
// speedup vs baseline: 1.2592x; 1.0623x over previous
#include <cuda_runtime.h>
#include <cuda_bf16.h>
#include <cuda_fp16.h>

#define BATCH   2048
#define NTOK    49
#define CH      512
#define NHEADS  4
#define KDIM    32
#define DV      128
#define QO      192
#define EPS     1e-5f
#define FST     136
#define KQS     40
#define ATS     72
#define ASF     52
#define YQS     36
#define NROWS   ((size_t)BATCH * NTOK)

// -------- global scratch --------
__device__ __align__(16) uint4 g_hA[NROWS * 128];
__device__ __align__(16) uint2 g_wBh[64 * 32 * 32];
__device__ __align__(16) uint2 g_qwB_hi[NHEADS * 24 * 8 * 32];
__device__ __align__(16) uint2 g_qwB_lo[NHEADS * 24 * 8 * 32];

// ==================== helpers ====================
__device__ __forceinline__ unsigned s2u(const void* p) {
    return (unsigned)__cvta_generic_to_shared(p);
}
__device__ __forceinline__ void ldsm_x4(unsigned* r, unsigned addr) {
    asm volatile("ldmatrix.sync.aligned.m8n8.x4.shared.b16 {%0,%1,%2,%3}, [%4];"
        : "=r"(r[0]), "=r"(r[1]), "=r"(r[2]), "=r"(r[3]) : "r"(addr));
}
__device__ __forceinline__ void ldsm_x4_t(unsigned* r, unsigned addr) {
    asm volatile("ldmatrix.sync.aligned.m8n8.x4.trans.shared.b16 {%0,%1,%2,%3}, [%4];"
        : "=r"(r[0]), "=r"(r[1]), "=r"(r[2]), "=r"(r[3]) : "r"(addr));
}
__device__ __forceinline__ void mma16816(float* c, const unsigned* a, const unsigned* b) {
    asm volatile("mma.sync.aligned.m16n8k16.row.col.f32.bf16.bf16.f32 "
        "{%0,%1,%2,%3}, {%4,%5,%6,%7}, {%8,%9}, {%0,%1,%2,%3};"
        : "+f"(c[0]), "+f"(c[1]), "+f"(c[2]), "+f"(c[3])
        : "r"(a[0]), "r"(a[1]), "r"(a[2]), "r"(a[3]), "r"(b[0]), "r"(b[1]));
}
__device__ __forceinline__ void mma16816h(float* c, const unsigned* a, const unsigned* b) {
    asm volatile("mma.sync.aligned.m16n8k16.row.col.f32.f16.f16.f32 "
        "{%0,%1,%2,%3}, {%4,%5,%6,%7}, {%8,%9}, {%0,%1,%2,%3};"
        : "+f"(c[0]), "+f"(c[1]), "+f"(c[2]), "+f"(c[3])
        : "r"(a[0]), "r"(a[1]), "r"(a[2]), "r"(a[3]), "r"(b[0]), "r"(b[1]));
}
__device__ __forceinline__ unsigned packbf2(float a, float b) {
    __nv_bfloat162 p = __halves2bfloat162(__float2bfloat16(a), __float2bfloat16(b));
    return *reinterpret_cast<unsigned*>(&p);
}
__device__ __forceinline__ void split2(float v0, float v1, unsigned& hp, unsigned& lp) {
    __nv_bfloat16 h0 = __float2bfloat16(v0), h1 = __float2bfloat16(v1);
    hp = (unsigned)__bfloat16_as_ushort(h0) | ((unsigned)__bfloat16_as_ushort(h1) << 16);
    lp = packbf2(v0 - __bfloat162float(h0), v1 - __bfloat162float(h1));
}
__device__ __forceinline__ unsigned packh2(__half a, __half b) {
    __half2 p = __halves2half2(a, b);
    return *reinterpret_cast<unsigned*>(&p);
}
__device__ __forceinline__ void split2h(float v0, float v1, unsigned& hp, unsigned& lp) {
    __half h0 = __float2half_rn(v0), h1 = __float2half_rn(v1);
    __half l0 = __float2half_rn(v0 - __half2float(h0));
    __half l1 = __float2half_rn(v1 - __half2float(h1));
    hp = packh2(h0, h1);
    lp = packh2(l0, l1);
}
__device__ __forceinline__ void pref_l1(const void* p) {
    asm volatile("prefetch.global.L1 [%0];" :: "l"(p));
}

// ==================== prep kernels ====================
__global__ void wsplit_kernel(const float* __restrict__ w) {
    int i = blockIdx.x * 256 + threadIdx.x;
    int j0 = i >> 10;
    int s_ = (i >> 5) & 31;
    int l  = i & 31;
    int n  = j0 * 8 + (l >> 2);
    int k0 = s_ * 16 + (l & 3) * 2;
    float a0 = w[n * 512 + k0],     a1 = w[n * 512 + k0 + 1];
    float a2 = w[n * 512 + k0 + 8], a3 = w[n * 512 + k0 + 9];
    uint2 p;
    p.x = packh2(__float2half_rn(a0), __float2half_rn(a1));
    p.y = packh2(__float2half_rn(a2), __float2half_rn(a3));
    g_wBh[i] = p;
}

__global__ void qkvsplit_kernel(const float* __restrict__ w) {
    int i = blockIdx.x * 256 + threadIdx.x;
    int h = i / (192 * 64);
    int rem = i % (192 * 64);
    int n = rem / 64;
    int p = rem % 64;
    float v0 = w[((size_t)h * 192 + n) * 128 + p * 2];
    float v1 = w[((size_t)h * 192 + n) * 128 + p * 2 + 1];
    unsigned hi, lo;
    split2(v0, v1, hi, lo);
    int j = n >> 3, kstep = p >> 3, q = p & 7;
    int r = q >> 2, lm4 = q & 3;
    int lane = (n & 7) * 4 + lm4;
    int base = ((h * 24 + j) * 8 + kstep) * 32 + lane;
    reinterpret_cast<unsigned*>(g_qwB_hi)[base * 2 + r] = hi;
    reinterpret_cast<unsigned*>(g_qwB_lo)[base * 2 + r] = lo;
}

// ==================== Phase A: cascaded heads ====================

struct __align__(16) SmemA {
    __nv_bfloat16 ah[64 * FST], al[64 * FST];
    __nv_bfloat16 vh[64 * FST], vl[64 * FST];
    union U1 {
        struct { __nv_bfloat16 kh[64 * KQS], kl[64 * KQS],
                               qh[64 * KQS], ql[64 * KQS]; } s1;
        struct { __nv_bfloat16 ath[64 * ATS], atl[64 * ATS]; } s2;
    } u1;
    union U2 { float attn[49 * ASF]; float yq[49 * YQS]; } u2;
    float dww[25 * 32];
    float qscale[NHEADS * QO], qbias[NHEADS * QO];
    float dws[NHEADS * KDIM], dwb[NHEADS * KDIM];
    float ab[NHEADS * NTOK];
};

__global__ void __launch_bounds__(256, 2) cascade_kernel(
    const float* __restrict__ x,
    const float* __restrict__ qkv_g,  const float* __restrict__ qkv_b,
    const float* __restrict__ qkv_m,  const float* __restrict__ qkv_v,
    const float* __restrict__ dw_w,   const float* __restrict__ dw_g,
    const float* __restrict__ dw_b,   const float* __restrict__ dw_m,
    const float* __restrict__ dw_v,   const float* __restrict__ attn_bias)
{
    extern __shared__ unsigned char smem_raw[];
    SmemA& s = *reinterpret_cast<SmemA*>(smem_raw);
    const int t    = threadIdx.x;
    const int b    = blockIdx.x;
    const int lane = t & 31;
    const int warp = t >> 5;
    const float scale = rsqrtf((float)KDIM);
    const size_t xoff = (size_t)b * NTOK * CH;

    for (int j = t; j < NHEADS * NTOK; j += 256) s.ab[j] = attn_bias[j];
    // all-heads BN folds, hoisted out of the head loop
    for (int j = t; j < NHEADS * QO; j += 256) {
        float sc = qkv_g[j] * rsqrtf(qkv_v[j] + EPS);
        s.qscale[j] = sc;
        s.qbias[j]  = qkv_b[j] - qkv_m[j] * sc;
    }
    if (t < NHEADS * KDIM) {
        float sc = dw_g[t] * rsqrtf(dw_v[t] + EPS);
        s.dws[t] = sc;
        s.dwb[t] = dw_b[t] - dw_m[t] * sc;
    }
    for (int j = t; j < 15 * FST; j += 256) {
        __nv_bfloat16 z = __float2bfloat16(0.f);
        s.ah[49 * FST + j] = z; s.al[49 * FST + j] = z;
        s.vh[49 * FST + j] = z; s.vl[49 * FST + j] = z;
    }
    if (t < 196) pref_l1(&x[xoff + (t >> 2) * CH + (t & 3) * 32]);

    const int a_r = lane & 15, a_c = (lane >> 4) * 8;
    const int b_r = (lane & 7) + ((lane & 16) ? 8 : 0);
    const int b_c = (lane & 8) ? 8 : 0;

    for (int head = 0; head < NHEADS; ++head) {
        // ---- feat update + hi/lo split, float4 batched loads (MLP 7) ----
        {
            float4 xv[7];
            #pragma unroll
            for (int it = 0; it < 7; ++it) {
                int c = t + it * 256;
                if (c < 1568) {
                    int n = c >> 5, d4 = (c & 31) * 4;
                    xv[it] = *reinterpret_cast<const float4*>(
                        &x[xoff + n * CH + head * 128 + d4]);
                }
            }
            #pragma unroll
            for (int it = 0; it < 7; ++it) {
                int c = t + it * 256;
                if (c < 1568) {
                    int n = c >> 5, d4 = (c & 31) * 4;
                    float v0 = xv[it].x, v1 = xv[it].y, v2 = xv[it].z, v3 = xv[it].w;
                    if (head > 0) {
                        uint2 uh = *reinterpret_cast<uint2*>(&s.ah[n * FST + d4]);
                        uint2 ul = *reinterpret_cast<uint2*>(&s.al[n * FST + d4]);
                        __nv_bfloat162 h0 = *reinterpret_cast<__nv_bfloat162*>(&uh.x);
                        __nv_bfloat162 h1 = *reinterpret_cast<__nv_bfloat162*>(&uh.y);
                        __nv_bfloat162 l0 = *reinterpret_cast<__nv_bfloat162*>(&ul.x);
                        __nv_bfloat162 l1 = *reinterpret_cast<__nv_bfloat162*>(&ul.y);
                        v0 += __low2float(h0) + __low2float(l0);
                        v1 += __high2float(h0) + __high2float(l0);
                        v2 += __low2float(h1) + __low2float(l1);
                        v3 += __high2float(h1) + __high2float(l1);
                    }
                    unsigned hp0, lp0, hp1, lp1;
                    split2(v0, v1, hp0, lp0);
                    split2(v2, v3, hp1, lp1);
                    *reinterpret_cast<uint2*>(&s.ah[n * FST + d4]) = make_uint2(hp0, hp1);
                    *reinterpret_cast<uint2*>(&s.al[n * FST + d4]) = make_uint2(lp0, lp1);
                }
            }
        }
        // per-head conv weights
        for (int j = t; j < KDIM * 25; j += 256) {
            int c = j / 25, tap = j % 25;
            s.dww[tap * 32 + c] = dw_w[(head * KDIM + c) * 25 + tap];
        }
        __syncthreads();

        // ================= qkv GEMM (mma, 3-term, B depth-2 pipeline) =================
        {
            float qacc[4][3][4];
            #pragma unroll
            for (int m = 0; m < 4; ++m)
                #pragma unroll
                for (int j = 0; j < 3; ++j)
                    #pragma unroll
                    for (int q = 0; q < 4; ++q) qacc[m][j][q] = 0.f;

            const int wbase = (head * 24 + warp * 3) * 8;
            uint2 bh0[3], bl0[3], bh1[3], bl1[3];
            #pragma unroll
            for (int j = 0; j < 3; ++j) {
                bh0[j] = g_qwB_hi[(wbase + j * 8 + 0) * 32 + lane];
                bl0[j] = g_qwB_lo[(wbase + j * 8 + 0) * 32 + lane];
                bh1[j] = g_qwB_hi[(wbase + j * 8 + 1) * 32 + lane];
                bl1[j] = g_qwB_lo[(wbase + j * 8 + 1) * 32 + lane];
            }
            #pragma unroll
            for (int k = 0; k < 8; ++k) {
                uint2 th[3], tl[3];
                if (k < 6) {
                    #pragma unroll
                    for (int j = 0; j < 3; ++j) {
                        th[j] = g_qwB_hi[(wbase + j * 8 + k + 2) * 32 + lane];
                        tl[j] = g_qwB_lo[(wbase + j * 8 + k + 2) * 32 + lane];
                    }
                }
                uint2* bhc = (k & 1) ? bh1 : bh0;
                uint2* blc = (k & 1) ? bl1 : bl0;
                #pragma unroll
                for (int m = 0; m < 4; ++m) {
                    unsigned Ah[4], Al[4];
                    ldsm_x4(Ah, s2u(&s.ah[(m * 16 + a_r) * FST + k * 16 + a_c]));
                    ldsm_x4(Al, s2u(&s.al[(m * 16 + a_r) * FST + k * 16 + a_c]));
                    #pragma unroll
                    for (int j = 0; j < 3; ++j) {
                        mma16816(qacc[m][j], Ah, reinterpret_cast<const unsigned*>(&bhc[j]));
                        mma16816(qacc[m][j], Ah, reinterpret_cast<const unsigned*>(&blc[j]));
                        mma16816(qacc[m][j], Al, reinterpret_cast<const unsigned*>(&bhc[j]));
                    }
                }
                if (k < 6) {
                    #pragma unroll
                    for (int j = 0; j < 3; ++j) {
                        if (k & 1) { bh1[j] = th[j]; bl1[j] = tl[j]; }
                        else       { bh0[j] = th[j]; bl0[j] = tl[j]; }
                    }
                }
            }
            // epilogue: BN fold -> yq (q fp32) | kh/kl | vh/vl
            const float* qsc = s.qscale + head * QO;
            const float* qbs = s.qbias  + head * QO;
            #pragma unroll
            for (int m = 0; m < 4; ++m) {
                int rb = m * 16 + (lane >> 2);
                #pragma unroll
                for (int j = 0; j < 3; ++j) {
                    int c0 = warp * 24 + j * 8 + (lane & 3) * 2;
                    float sc0 = qsc[c0], sc1 = qsc[c0 + 1];
                    float bb0 = qbs[c0], bb1 = qbs[c0 + 1];
                    #pragma unroll
                    for (int h2 = 0; h2 < 2; ++h2) {
                        int r = rb + h2 * 8;
                        if (r < NTOK) {
                            float y0 = qacc[m][j][h2 * 2 + 0] * sc0 + bb0;
                            float y1 = qacc[m][j][h2 * 2 + 1] * sc1 + bb1;
                            if (c0 < 32) {
                                s.u2.yq[r * YQS + c0]     = y0;
                                s.u2.yq[r * YQS + c0 + 1] = y1;
                            } else if (c0 < 64) {
                                unsigned hp, lp;
                                split2(y0, y1, hp, lp);
                                *reinterpret_cast<unsigned*>(&s.u1.s1.kh[r * KQS + c0 - 32]) = hp;
                                *reinterpret_cast<unsigned*>(&s.u1.s1.kl[r * KQS + c0 - 32]) = lp;
                            } else {
                                unsigned hp, lp;
                                split2(y0, y1, hp, lp);
                                *reinterpret_cast<unsigned*>(&s.vh[r * FST + c0 - 64]) = hp;
                                *reinterpret_cast<unsigned*>(&s.vl[r * FST + c0 - 64]) = lp;
                            }
                        }
                    }
                }
            }
        }
        __syncthreads();

        // ================= depthwise 5x5 conv (+BN) -> qh/ql =================
        for (int idx = t; idx < NTOK * KDIM; idx += 256) {
            int n = idx >> 5, c = idx & 31;
            int r = n / 7, sc_ = n % 7;
            float sum = 0.f;
            #pragma unroll
            for (int a = 0; a < 5; ++a) {
                int rr = r + a - 2;
                if ((unsigned)rr < 7u) {
                    #pragma unroll
                    for (int bb = 0; bb < 5; ++bb) {
                        int ss = sc_ + bb - 2;
                        if ((unsigned)ss < 7u)
                            sum += s.u2.yq[(rr * 7 + ss) * YQS + c] * s.dww[(a * 5 + bb) * 32 + c];
                    }
                }
            }
            float qv = sum * s.dws[head * KDIM + c] + s.dwb[head * KDIM + c];
            __nv_bfloat16 hv = __float2bfloat16(qv);
            s.u1.s1.qh[n * KQS + c] = hv;
            s.u1.s1.ql[n * KQS + c] = __float2bfloat16(qv - __bfloat162float(hv));
        }
        __syncthreads();

        // ================= qk scores (mma, 3-term) =================
        {
            const int wm = (warp & 3) * 16, wn = (warp >> 2) * 32;
            float sacc[4][4];
            #pragma unroll
            for (int nt = 0; nt < 4; ++nt)
                #pragma unroll
                for (int q = 0; q < 4; ++q) sacc[nt][q] = 0.f;

            #pragma unroll
            for (int k16 = 0; k16 < 2; ++k16) {
                unsigned Ah[4], Al[4];
                ldsm_x4(Ah, s2u(&s.u1.s1.qh[(wm + a_r) * KQS + k16 * 16 + a_c]));
                ldsm_x4(Al, s2u(&s.u1.s1.ql[(wm + a_r) * KQS + k16 * 16 + a_c]));
                unsigned Bh[2][4], Bl[2][4];
                #pragma unroll
                for (int g = 0; g < 2; ++g) {
                    ldsm_x4(Bh[g], s2u(&s.u1.s1.kh[(wn + g * 16 + b_r) * KQS + k16 * 16 + b_c]));
                    ldsm_x4(Bl[g], s2u(&s.u1.s1.kl[(wn + g * 16 + b_r) * KQS + k16 * 16 + b_c]));
                }
                #pragma unroll
                for (int nt = 0; nt < 4; ++nt) {
                    const unsigned* bh = &Bh[nt >> 1][(nt & 1) * 2];
                    const unsigned* bl = &Bl[nt >> 1][(nt & 1) * 2];
                    mma16816(sacc[nt], Ah, bh);
                    mma16816(sacc[nt], Ah, bl);
                    mma16816(sacc[nt], Al, bh);
                }
            }
            const float* abr = s.ab + head * NTOK;
            int r0 = wm + (lane >> 2);
            #pragma unroll
            for (int nt = 0; nt < 4; ++nt) {
                int c0 = wn + nt * 8 + (lane & 3) * 2;
                #pragma unroll
                for (int h2 = 0; h2 < 2; ++h2) {
                    int r = r0 + h2 * 8;
                    if (r < NTOK) {
                        int rr7 = r / 7, rm7 = r % 7;
                        #pragma unroll
                        for (int q = 0; q < 2; ++q) {
                            int c = c0 + q;
                            if (c < NTOK) {
                                int cd = c / 7, cm = c % 7;
                                int bi = abs(rr7 - cd) * 7 + abs(rm7 - cm);
                                s.u2.attn[r * ASF + c] =
                                    sacc[nt][h2 * 2 + q] * scale + abr[bi];
                            }
                        }
                    }
                }
            }
        }
        __syncthreads();

        // ================= softmax -> ath/atl =================
        for (int r = warp; r < NTOK; r += 8) {
            float a = s.u2.attn[r * ASF + lane];
            bool hasb = (lane + 32) < NTOK;
            float bv = hasb ? s.u2.attn[r * ASF + 32 + lane] : -1e30f;
            float mx = fmaxf(a, bv);
            #pragma unroll
            for (int off = 16; off > 0; off >>= 1)
                mx = fmaxf(mx, __shfl_xor_sync(0xffffffffu, mx, off));
            float ea = __expf(a - mx);
            float eb = hasb ? __expf(bv - mx) : 0.f;
            float sm = ea + eb;
            #pragma unroll
            for (int off = 16; off > 0; off >>= 1)
                sm += __shfl_xor_sync(0xffffffffu, sm, off);
            float inv = __frcp_rn(sm);
            float pa = ea * inv, pb = eb * inv;
            __nv_bfloat16 ph = __float2bfloat16(pa);
            s.u1.s2.ath[r * ATS + lane] = ph;
            s.u1.s2.atl[r * ATS + lane] = __float2bfloat16(pa - __bfloat162float(ph));
            if (hasb) {
                __nv_bfloat16 qh2 = __float2bfloat16(pb);
                s.u1.s2.ath[r * ATS + 32 + lane] = qh2;
                s.u1.s2.atl[r * ATS + 32 + lane] = __float2bfloat16(pb - __bfloat162float(qh2));
            }
            if (lane < 15) {
                __nv_bfloat16 z = __float2bfloat16(0.f);
                s.u1.s2.ath[r * ATS + 49 + lane] = z;
                s.u1.s2.atl[r * ATS + 49 + lane] = z;
            }
        }
        __syncthreads();

        // ================= attn @ v (mma, 3-term) =================
        {
            const int wm2 = (warp & 1) * 32, wn2 = (warp >> 1) * 32;
            float facc[2][4][4];
            #pragma unroll
            for (int mt = 0; mt < 2; ++mt)
                #pragma unroll
                for (int nt = 0; nt < 4; ++nt)
                    #pragma unroll
                    for (int q = 0; q < 4; ++q) facc[mt][nt][q] = 0.f;

            #pragma unroll
            for (int k16 = 0; k16 < 4; ++k16) {
                unsigned Ah[2][4], Al[2][4];
                #pragma unroll
                for (int mt = 0; mt < 2; ++mt) {
                    ldsm_x4(Ah[mt], s2u(&s.u1.s2.ath[(wm2 + mt * 16 + a_r) * ATS + k16 * 16 + a_c]));
                    ldsm_x4(Al[mt], s2u(&s.u1.s2.atl[(wm2 + mt * 16 + a_r) * ATS + k16 * 16 + a_c]));
                }
                unsigned Bh[2][4], Bl[2][4];
                #pragma unroll
                for (int g = 0; g < 2; ++g) {
                    unsigned addr_h = s2u(&s.vh[(k16 * 16 + (lane & 15)) * FST +
                                                wn2 + g * 16 + (lane >> 4) * 8]);
                    unsigned addr_l = s2u(&s.vl[(k16 * 16 + (lane & 15)) * FST +
                                                wn2 + g * 16 + (lane >> 4) * 8]);
                    ldsm_x4_t(Bh[g], addr_h);
                    ldsm_x4_t(Bl[g], addr_l);
                }
                #pragma unroll
                for (int mt = 0; mt < 2; ++mt)
                    #pragma unroll
                    for (int nt = 0; nt < 4; ++nt) {
                        const unsigned* bh = &Bh[nt >> 1][(nt & 1) * 2];
                        const unsigned* bl = &Bl[nt >> 1][(nt & 1) * 2];
                        mma16816(facc[mt][nt], Ah[mt], bh);
                        mma16816(facc[mt][nt], Ah[mt], bl);
                        mma16816(facc[mt][nt], Al[mt], bh);
                    }
            }
            // epilogue: new feat (ah/al bf16) + relu to g_hA (fp16 hi/lo)
            #pragma unroll
            for (int mt = 0; mt < 2; ++mt)
                #pragma unroll
                for (int nt = 0; nt < 4; ++nt) {
                    int c0 = wn2 + nt * 8 + (lane & 3) * 2;
                    int C  = head * 128 + c0;
                    int kstep = C >> 4, jj = C & 15;
                    int quad = (jj < 8) ? (jj >> 1) : ((jj - 8) >> 1);
                    int word = (jj < 8) ? 0 : 1;
                    #pragma unroll
                    for (int h2 = 0; h2 < 2; ++h2) {
                        int r = wm2 + mt * 16 + (lane >> 2) + h2 * 8;
                        if (r < NTOK) {
                            float v0 = facc[mt][nt][h2 * 2 + 0];
                            float v1 = facc[mt][nt][h2 * 2 + 1];
                            unsigned hp, lp;
                            split2(v0, v1, hp, lp);
                            *reinterpret_cast<unsigned*>(&s.ah[r * FST + c0]) = hp;
                            *reinterpret_cast<unsigned*>(&s.al[r * FST + c0]) = lp;
                            float r0v = fmaxf(v0, 0.f), r1v = fmaxf(v1, 0.f);
                            unsigned ghp, glp;
                            split2h(r0v, r1v, ghp, glp);
                            size_t row = (size_t)b * NTOK + r;
                            size_t idx = (row >> 4) * 2048 + (size_t)kstep * 64 +
                                         (row & 15) * 4 + quad;
                            unsigned* up = reinterpret_cast<unsigned*>(&g_hA[idx]);
                            up[word]     = ghp;
                            up[word + 2] = glp;
                        }
                    }
                }
        }
        if (head < NHEADS - 1 && t < 196)
            pref_l1(&x[xoff + (t >> 2) * CH + (head + 1) * 128 + (t & 3) * 32]);
        __syncthreads();
    }
}

// ==================== Phase B: projection — fp16 2-term, pointer-incremented LDG ====================

__global__ void __launch_bounds__(256, 2) proj_mma_kernel(
    const float* __restrict__ proj_g, const float* __restrict__ proj_b,
    const float* __restrict__ proj_m, const float* __restrict__ proj_v,
    float* __restrict__ out)
{
    __shared__ float sPs[64], sPb[64];

    const int t = threadIdx.x, lane = t & 31, warp = t >> 5;
    const int row0 = blockIdx.y * 128, col0 = blockIdx.x * 64;

    if (t < 64) {
        int o = col0 + t;
        float sc = proj_g[o] * rsqrtf(proj_v[o] + EPS);
        sPs[t] = sc;
        sPb[t] = proj_b[o] - proj_m[o] * sc;
    }
    __syncthreads();

    const int wm = (warp >> 1) * 32, wn = (warp & 1) * 32;
    const int nb = (col0 >> 3) + (wn >> 3);

    float acc[2][4][4];
    #pragma unroll
    for (int mt = 0; mt < 2; ++mt)
        #pragma unroll
        for (int nt = 0; nt < 4; ++nt)
            #pragma unroll
            for (int q = 0; q < 4; ++q) acc[mt][nt][q] = 0.f;

    const int tile0 = (row0 + wm) >> 4;

    const uint4* pA0 = g_hA + (size_t)tile0 * 2048 + lane;
    const uint4* pA1 = g_hA + (size_t)(tile0 + 1) * 2048 + lane;
    const uint2* pW0 = g_wBh + (size_t)(nb + 0) * 1024 + lane;
    const uint2* pW1 = g_wBh + (size_t)(nb + 1) * 1024 + lane;
    const uint2* pW2 = g_wBh + (size_t)(nb + 2) * 1024 + lane;
    const uint2* pW3 = g_wBh + (size_t)(nb + 3) * 1024 + lane;

    for (int ks = 0; ks < 32; ++ks) {
        unsigned Ah[2][4], Al[2][4];
        {
            uint4 U0 = pA0[0], U1 = pA0[32];
            Ah[0][0] = U0.x; Ah[0][1] = U1.x; Ah[0][2] = U0.y; Ah[0][3] = U1.y;
            Al[0][0] = U0.z; Al[0][1] = U1.z; Al[0][2] = U0.w; Al[0][3] = U1.w;
            uint4 V0 = pA1[0], V1 = pA1[32];
            Ah[1][0] = V0.x; Ah[1][1] = V1.x; Ah[1][2] = V0.y; Ah[1][3] = V1.y;
            Al[1][0] = V0.z; Al[1][1] = V1.z; Al[1][2] = V0.w; Al[1][3] = V1.w;
        }
        uint2 W[4];
        W[0] = pW0[0]; W[1] = pW1[0]; W[2] = pW2[0]; W[3] = pW3[0];
        pA0 += 64; pA1 += 64;
        pW0 += 32; pW1 += 32; pW2 += 32; pW3 += 32;

        #pragma unroll
        for (int mt = 0; mt < 2; ++mt)
            #pragma unroll
            for (int nt = 0; nt < 4; ++nt) {
                const unsigned* bw = reinterpret_cast<const unsigned*>(&W[nt]);
                mma16816h(acc[mt][nt], Ah[mt], bw);
                mma16816h(acc[mt][nt], Al[mt], bw);
            }
    }

    const int er = lane >> 2, ec = (lane & 3) * 2;
    #pragma unroll
    for (int mt = 0; mt < 2; ++mt)
        #pragma unroll
        for (int nt = 0; nt < 4; ++nt) {
            int cl = wn + nt * 8 + ec;
            float s0 = sPs[cl], s1 = sPs[cl + 1];
            float b0 = sPb[cl], b1 = sPb[cl + 1];
            size_t gr = (size_t)(row0 + wm + mt * 16 + er) * 512 + col0 + cl;
            *reinterpret_cast<float2*>(&out[gr]) =
                make_float2(acc[mt][nt][0] * s0 + b0, acc[mt][nt][1] * s1 + b1);
            *reinterpret_cast<float2*>(&out[gr + (size_t)8 * 512]) =
                make_float2(acc[mt][nt][2] * s0 + b0, acc[mt][nt][3] * s1 + b1);
        }
}

// ==================== launch ====================

extern "C" void kernel_launch(void* const* d_in, const int* in_sizes, int n_in,
                              void* d_out, int out_size) {
    const float* x         = (const float*)d_in[0];
    const float* qkv_w     = (const float*)d_in[1];
    const float* qkv_g     = (const float*)d_in[2];
    const float* qkv_b     = (const float*)d_in[3];
    const float* qkv_m     = (const float*)d_in[4];
    const float* qkv_v     = (const float*)d_in[5];
    const float* dw_w      = (const float*)d_in[6];
    const float* dw_g      = (const float*)d_in[7];
    const float* dw_b      = (const float*)d_in[8];
    const float* dw_m      = (const float*)d_in[9];
    const float* dw_v      = (const float*)d_in[10];
    const float* proj_w    = (const float*)d_in[11];
    const float* proj_g    = (const float*)d_in[12];
    const float* proj_b    = (const float*)d_in[13];
    const float* proj_m    = (const float*)d_in[14];
    const float* proj_v    = (const float*)d_in[15];
    const float* attn_bias = (const float*)d_in[16];
    float* out = (float*)d_out;

    cudaFuncSetAttribute(cascade_kernel,
                         cudaFuncAttributeMaxDynamicSharedMemorySize,
                         (int)sizeof(SmemA));

    wsplit_kernel<<<256, 256>>>(proj_w);
    qkvsplit_kernel<<<192, 256>>>(qkv_w);

    cascade_kernel<<<BATCH, 256, sizeof(SmemA)>>>(
        x, qkv_g, qkv_b, qkv_m, qkv_v,
        dw_w, dw_g, dw_b, dw_m, dw_v, attn_bias);

    proj_mma_kernel<<<dim3(8, 784), 256>>>(proj_g, proj_b, proj_m, proj_v, out);
}